// round 4
// baseline (speedup 1.0000x reference)
#include <cuda_runtime.h>

#define BATCH 8
#define NPTS  8192
#define NS    2048      // S = 0.25 * N
#define KNB   32        // nsample
#define C1    64
#define C2    64
#define C3    128

// scratch shared between producer (FPS) and consumer (ball-query+MLP) CTAs
__device__ float g_new_xyz[BATCH * NS * 3];
__device__ int   g_prog[BATCH];          // centers produced so far, per batch

// XLA-exact squared distance: ((dx*dx + dy*dy) + dz*dz), no FMA contraction
__device__ __forceinline__ float sqdist_xla(float dx, float dy, float dz) {
    return __fadd_rn(__fadd_rn(__fmul_rn(dx, dx), __fmul_rn(dy, dy)),
                     __fmul_rn(dz, dz));
}

__device__ __forceinline__ unsigned long long pack2(float a, float b) {
    unsigned long long r;
    asm("mov.b64 %0, {%1, %2};" : "=l"(r) : "f"(a), "f"(b));
    return r;
}
__device__ __forceinline__ void unpack2(unsigned long long v, float& a, float& b) {
    asm("mov.b64 {%0, %1}, %2;" : "=f"(a), "=f"(b) : "l"(v));
}
__device__ __forceinline__ unsigned long long add2(unsigned long long a, unsigned long long b) {
    unsigned long long r;
    asm("add.rn.f32x2 %0, %1, %2;" : "=l"(r) : "l"(a), "l"(b));
    return r;
}
__device__ __forceinline__ unsigned long long mul2(unsigned long long a, unsigned long long b) {
    unsigned long long r;
    asm("mul.rn.f32x2 %0, %1, %2;" : "=l"(r) : "l"(a), "l"(b));
    return r;
}

__global__ void reset_kernel() {
    if (threadIdx.x < BATCH) g_prog[threadIdx.x] = 0;
}

// ---------------------------------------------------------------------------
// Producer: farthest point sampling for batch b (one 256-thread CTA).
// Identical math to R3 (bit-exact). After writing center s, releases
// g_prog[b] = s+1 so consumer CTAs can proceed.
// ---------------------------------------------------------------------------
__device__ void fps_producer(const float* __restrict__ xyz,
                             float* __restrict__ out, int b)
{
    const int tid = threadIdx.x;
    const int lane = tid & 31, wid = tid >> 5;
    const float* P = xyz + b * NPTS * 3;

    __shared__ float sV[2][8];
    __shared__ int   sI[2][8];

    unsigned long long npx[16], npy[16], npz[16];
    float dist[32];
#pragma unroll
    for (int m = 0; m < 16; m++) {
        int i0 = tid + (2 * m) * 256;
        int i1 = tid + (2 * m + 1) * 256;
        npx[m] = pack2(-P[i0 * 3 + 0], -P[i1 * 3 + 0]);
        npy[m] = pack2(-P[i0 * 3 + 1], -P[i1 * 3 + 1]);
        npz[m] = pack2(-P[i0 * 3 + 2], -P[i1 * 3 + 2]);
        dist[2 * m] = 1e10f;
        dist[2 * m + 1] = 1e10f;
    }
    float cx = __ldg(P + 0), cy = __ldg(P + 1), cz = __ldg(P + 2);

    for (int s = 0; s < NS; s++) {
        if (tid == 0) {
            int o = b * 3 * NS + s;          // (B,3,S) transposed output
            out[o]          = cx;
            out[o + NS]     = cy;
            out[o + 2 * NS] = cz;
            int c = (b * NS + s) * 3;
            g_new_xyz[c]     = cx;
            g_new_xyz[c + 1] = cy;
            g_new_xyz[c + 2] = cz;
            // publish: release orders the 6 stores above before the flag
            asm volatile("st.release.gpu.global.s32 [%0], %1;"
                         :: "l"(&g_prog[b]), "r"(s + 1) : "memory");
        }

        const unsigned long long cxx = pack2(cx, cx);
        const unsigned long long cyy = pack2(cy, cy);
        const unsigned long long czz = pack2(cz, cz);

        float bv = -1.0f;
        int   bi = 0;
#pragma unroll
        for (int m = 0; m < 16; m++) {
            unsigned long long dx2 = add2(cxx, npx[m]);   // cx - px (exact)
            unsigned long long dy2 = add2(cyy, npy[m]);
            unsigned long long dz2 = add2(czz, npz[m]);
            unsigned long long d2p = add2(add2(mul2(dx2, dx2), mul2(dy2, dy2)),
                                          mul2(dz2, dz2)); // ((x²+y²)+z²) rn
            float d0, d1;
            unpack2(d2p, d0, d1);
            float nd0 = fminf(dist[2 * m], d0);
            dist[2 * m] = nd0;
            if (nd0 > bv) { bv = nd0; bi = tid + (2 * m) * 256; }
            float nd1 = fminf(dist[2 * m + 1], d1);
            dist[2 * m + 1] = nd1;
            if (nd1 > bv) { bv = nd1; bi = tid + (2 * m + 1) * 256; }
        }

        // warp argmax reduce (lexicographic: max value, then lowest index)
#pragma unroll
        for (int off = 16; off; off >>= 1) {
            float ov = __shfl_down_sync(0xffffffffu, bv, off);
            int   oi = __shfl_down_sync(0xffffffffu, bi, off);
            if (ov > bv || (ov == bv && oi < bi)) { bv = ov; bi = oi; }
        }
        const int pb = s & 1;
        if (lane == 0) { sV[pb][wid] = bv; sI[pb][wid] = bi; }
        __syncthreads();

        // every thread reduces the 8 warp candidates redundantly
        float xv = sV[pb][0];
        int   xi = sI[pb][0];
#pragma unroll
        for (int w = 1; w < 8; w++) {
            float cv = sV[pb][w];
            int   ci = sI[pb][w];
            if (cv > xv || (cv == xv && ci < xi)) { xv = cv; xi = ci; }
        }
        cx = __ldg(P + xi * 3 + 0);   // L1-resident broadcast
        cy = __ldg(P + xi * 3 + 1);
        cz = __ldg(P + xi * 3 + 2);
    }
}

// ---------------------------------------------------------------------------
// Consumer: ball-query + grouping + 3-layer MLP + max-pool for one s across
// all 8 batches (warp w = batch w). Spins on g_prog[b] until center s is
// published, then reads the centroid via L2 (__ldcg).
// ---------------------------------------------------------------------------
__device__ void bq_mlp_consumer(const float* __restrict__ xyz,
                                const float* __restrict__ w1, const float* __restrict__ b1,
                                const float* __restrict__ w2, const float* __restrict__ b2,
                                const float* __restrict__ w3, const float* __restrict__ b3,
                                float* __restrict__ out, int s, float* sh, int* sNbrAll)
{
    float* sW1  = sh;                    // 192
    float* sB1  = sW1 + C1 * 3;          // 64
    float* sW2t = sB1 + C1;              // 4096 (transposed: [i][o])
    float* sB2  = sW2t + C2 * C1;        // 64
    float* sW3  = sB2 + C2;              // 8192
    float* sB3  = sW3 + C3 * C2;         // 128

    const int tid = threadIdx.x;
    for (int i = tid; i < C1 * 3;  i += 256) sW1[i] = w1[i];
    for (int i = tid; i < C1;      i += 256) sB1[i] = b1[i];
    for (int i = tid; i < C2 * C1; i += 256) {
        int o = i >> 6, ii = i & 63;
        sW2t[ii * C2 + o] = w2[i];
    }
    for (int i = tid; i < C2;      i += 256) sB2[i] = b2[i];
    for (int i = tid; i < C3 * C2; i += 256) sW3[i] = w3[i];
    for (int i = tid; i < C3;      i += 256) sB3[i] = b3[i];
    __syncthreads();

    const int wid  = tid >> 5;
    const int lane = tid & 31;
    const int b    = wid;                       // warp = batch
    const float* P = xyz + b * NPTS * 3;

    // wait until center s of batch b is published
    const int need = s + 1;
    for (;;) {
        int p;
        asm volatile("ld.acquire.gpu.global.s32 %0, [%1];"
                     : "=r"(p) : "l"(&g_prog[b]) : "memory");
        if (p >= need) break;
        __nanosleep(128);
    }
    const int cbase = (b * NS + s) * 3;
    const float cx = __ldcg(&g_new_xyz[cbase + 0]);   // L2 read (fresh)
    const float cy = __ldcg(&g_new_xyz[cbase + 1]);
    const float cz = __ldcg(&g_new_xyz[cbase + 2]);

    // ---- ball query: first KNB hits in ascending index order ----
    const float RR = 0.04f;   // JAX weak-typed (0.2*0.2) double -> f32
    int count = 0;
    int* nb = sNbrAll + wid * KNB;
    for (int base = 0; base < NPTS && count < KNB; base += 32) {
        int i = base + lane;
        float dx = cx - P[i * 3 + 0];
        float dy = cy - P[i * 3 + 1];
        float dz = cz - P[i * 3 + 2];
        float d2 = sqdist_xla(dx, dy, dz);
        bool hit = (d2 <= RR);
        unsigned m = __ballot_sync(0xffffffffu, hit);
        int pos = count + __popc(m & ((1u << lane) - 1u));
        if (hit && pos < KNB) nb[pos] = i;
        count += __popc(m);
    }
    __syncwarp();
    int cc = count < KNB ? count : KNB;   // >= 1 always
    if (lane >= cc) nb[lane] = nb[0];     // pad with first hit
    __syncwarp();
    const int ni = nb[lane];

    const float rx = P[ni * 3 + 0] - cx;
    const float ry = P[ni * 3 + 1] - cy;
    const float rz = P[ni * 3 + 2] - cz;

    // ---- layers 1+2 fused: h2[o] = b2[o] + sum_i W2[o][i]*relu(W1[i]·rel+b1[i])
    float acc[C2];
#pragma unroll
    for (int o = 0; o < C2; o++) acc[o] = sB2[o];

#pragma unroll 4
    for (int i = 0; i < C1; i++) {
        float a = sB1[i];
        a = fmaf(sW1[i * 3 + 0], rx, a);
        a = fmaf(sW1[i * 3 + 1], ry, a);
        a = fmaf(sW1[i * 3 + 2], rz, a);
        float h1 = fmaxf(a, 0.0f);
        const float4* w4 = reinterpret_cast<const float4*>(sW2t + (i << 6));
#pragma unroll
        for (int o4 = 0; o4 < 16; o4++) {
            float4 w = w4[o4];
            acc[o4 * 4 + 0] = fmaf(w.x, h1, acc[o4 * 4 + 0]);
            acc[o4 * 4 + 1] = fmaf(w.y, h1, acc[o4 * 4 + 1]);
            acc[o4 * 4 + 2] = fmaf(w.z, h1, acc[o4 * 4 + 2]);
            acc[o4 * 4 + 3] = fmaf(w.w, h1, acc[o4 * 4 + 3]);
        }
    }
#pragma unroll
    for (int o = 0; o < C2; o++) acc[o] = fmaxf(acc[o], 0.0f);

    // ---- layer 3: 64 -> 128, streamed, warp max over 32 neighbors ----
    float* optr = out + BATCH * 3 * NS + (b * C3) * NS + s;
#pragma unroll 2
    for (int o = 0; o < C3; o++) {
        const float4* w4 = reinterpret_cast<const float4*>(sW3 + (o << 6));
        float a = sB3[o];
#pragma unroll
        for (int i4 = 0; i4 < 16; i4++) {
            float4 w = w4[i4];
            a = fmaf(w.x, acc[i4 * 4 + 0], a);
            a = fmaf(w.y, acc[i4 * 4 + 1], a);
            a = fmaf(w.z, acc[i4 * 4 + 2], a);
            a = fmaf(w.w, acc[i4 * 4 + 3], a);
        }
        a = fmaxf(a, 0.0f);
#pragma unroll
        for (int off = 16; off; off >>= 1)
            a = fmaxf(a, __shfl_xor_sync(0xffffffffu, a, off));
        if (lane == 0) optr[o * NS] = a;
    }
}

// ---------------------------------------------------------------------------
// Fused kernel: CTAs 0..7 are FPS producers (wave-1 resident, never wait),
// CTAs 8..2055 are consumers (CTA 8+s handles center s for all 8 batches).
// ---------------------------------------------------------------------------
__global__ __launch_bounds__(256) void fused_kernel(
    const float* __restrict__ xyz,
    const float* __restrict__ w1, const float* __restrict__ b1,
    const float* __restrict__ w2, const float* __restrict__ b2,
    const float* __restrict__ w3, const float* __restrict__ b3,
    float* __restrict__ out)
{
    extern __shared__ float sh[];
    if (blockIdx.x < BATCH) {
        fps_producer(xyz, out, blockIdx.x);
    } else {
        int* sNbrAll = (int*)(sh + C1 * 3 + C1 + C2 * C1 + C2 + C3 * C2 + C3);
        bq_mlp_consumer(xyz, w1, b1, w2, b2, w3, b3, out,
                        blockIdx.x - BATCH, sh, sNbrAll);
    }
}

// ---------------------------------------------------------------------------
extern "C" void kernel_launch(void* const* d_in, const int* in_sizes, int n_in,
                              void* d_out, int out_size)
{
    const float* xyz = (const float*)d_in[0];
    // d_in[1] = features, unused by the reference
    const float* w1 = (const float*)d_in[2];
    const float* b1 = (const float*)d_in[3];
    const float* w2 = (const float*)d_in[4];
    const float* b2 = (const float*)d_in[5];
    const float* w3 = (const float*)d_in[6];
    const float* b3 = (const float*)d_in[7];
    float* out = (float*)d_out;

    const int shmem = (C1 * 3 + C1 + C2 * C1 + C2 + C3 * C2 + C3) * 4 + 8 * KNB * 4;
    cudaFuncSetAttribute(fused_kernel, cudaFuncAttributeMaxDynamicSharedMemorySize, shmem);

    reset_kernel<<<1, 32>>>();
    fused_kernel<<<BATCH + NS, 256, shmem>>>(xyz, w1, b1, w2, b2, w3, b3, out);
}